// round 15
// baseline (speedup 1.0000x reference)
#include <cuda_runtime.h>
#include <math.h>

// Problem constants (fixed by the reference)
#define NODES 100000
#define F 128          // feature width of every layer input/output (HEADS*HID)
#define NF (NODES * F)
#define N4 (NODES * 4)

// ---------------------------------------------------------------------------
// Scratch (device globals -- no allocation allowed)
// ---------------------------------------------------------------------------
__device__ float g_xw[NF];     // xw = input @ W for current layer  [N,4,32]
__device__ float g_acc[NF];    // per-dst weighted message accumulator
__device__ float g_h[NF];      // activations feeding the next layer
__device__ float g_ssrc[N4];   // per-node source attention logits  [N,4]
__device__ float g_sdst[N4];   // per-node dest   attention logits  [N,4]
__device__ float g_amax[N4];   // segment max per (dst, head)
__device__ float g_den[N4];    // segment softmax denominator

__device__ __forceinline__ float lrelu(float x) { return x > 0.f ? x : 0.2f * x; }

__device__ __forceinline__ void atomicMaxF(float* a, float v) {
    if (v >= 0.f) atomicMax((int*)a, __float_as_int(v));
    else          atomicMin((unsigned int*)a, __float_as_uint(v));
}

// ---------------------------------------------------------------------------
// init: acc = 0, amax = -inf, den = 0
// ---------------------------------------------------------------------------
__global__ void zero_kernel() {
    int idx = blockIdx.x * blockDim.x + threadIdx.x;
    if (idx < NF) g_acc[idx] = 0.f;
    if (idx < N4) {
        g_amax[idx] = __int_as_float(0xff800000);  // -inf
        g_den[idx]  = 0.f;
    }
}

// ---------------------------------------------------------------------------
// SGEMM: g_xw = A[M,128] @ W[128,128]    (BM=BN=128, BK=16, 8x8 per thread)
// use_h selects the g_h global as input (layers 2,3)
// ---------------------------------------------------------------------------
#define BK 16
#define ASTRIDE 132   // padded, keeps float4 alignment & spreads banks

__global__ __launch_bounds__(256) void sgemm128(const float* __restrict__ Ain,
                                                const float* __restrict__ B,
                                                int M, int use_h)
{
    const float* A = use_h ? g_h : Ain;
    __shared__ float As[BK * ASTRIDE];
    __shared__ float Bs[BK * 128];

    int tid  = threadIdx.x;
    int row0 = blockIdx.x * 128;
    int tx   = tid & 15;
    int ty   = tid >> 4;

    float acc[8][8];
#pragma unroll
    for (int r = 0; r < 8; r++)
#pragma unroll
        for (int c = 0; c < 8; c++) acc[r][c] = 0.f;

    for (int kt = 0; kt < F; kt += BK) {
        // A tile: 128 rows x 16 k, stored transposed As[k][row]
#pragma unroll
        for (int i = 0; i < 2; i++) {
            int f4  = tid * 2 + i;          // 0..511
            int row = f4 >> 2;
            int q4  = (f4 & 3) * 4;
            float4 v = make_float4(0.f, 0.f, 0.f, 0.f);
            int gr = row0 + row;
            if (gr < M) v = *(const float4*)&A[gr * F + kt + q4];
            As[(q4 + 0) * ASTRIDE + row] = v.x;
            As[(q4 + 1) * ASTRIDE + row] = v.y;
            As[(q4 + 2) * ASTRIDE + row] = v.z;
            As[(q4 + 3) * ASTRIDE + row] = v.w;
        }
        // B tile: 16 k x 128 cols
#pragma unroll
        for (int i = 0; i < 2; i++) {
            int f4 = tid * 2 + i;
            int k  = f4 >> 5;
            int j4 = (f4 & 31) * 4;
            *(float4*)&Bs[k * 128 + j4] = *(const float4*)&B[(kt + k) * F + j4];
        }
        __syncthreads();

#pragma unroll
        for (int kk = 0; kk < BK; kk++) {
            float4 a0 = *(const float4*)&As[kk * ASTRIDE + ty * 8];
            float4 a1 = *(const float4*)&As[kk * ASTRIDE + ty * 8 + 4];
            float4 b0 = *(const float4*)&Bs[kk * 128 + tx * 8];
            float4 b1 = *(const float4*)&Bs[kk * 128 + tx * 8 + 4];
            float av[8] = {a0.x, a0.y, a0.z, a0.w, a1.x, a1.y, a1.z, a1.w};
            float bv[8] = {b0.x, b0.y, b0.z, b0.w, b1.x, b1.y, b1.z, b1.w};
#pragma unroll
            for (int r = 0; r < 8; r++)
#pragma unroll
                for (int c = 0; c < 8; c++) acc[r][c] += av[r] * bv[c];
        }
        __syncthreads();
    }

#pragma unroll
    for (int r = 0; r < 8; r++) {
        int gr = row0 + ty * 8 + r;
        if (gr >= M) continue;
        float4 v0 = make_float4(acc[r][0], acc[r][1], acc[r][2], acc[r][3]);
        float4 v1 = make_float4(acc[r][4], acc[r][5], acc[r][6], acc[r][7]);
        *(float4*)&g_xw[gr * F + tx * 8]     = v0;
        *(float4*)&g_xw[gr * F + tx * 8 + 4] = v1;
    }
}

// ---------------------------------------------------------------------------
// Per-node attention logits: s_src[i,h] = sum_c xw[i,h,c]*a_src[h,c]  (warp/row)
// ---------------------------------------------------------------------------
__global__ void scores_kernel(const float* __restrict__ a_s,
                              const float* __restrict__ a_d, int n)
{
    int warp = (blockIdx.x * blockDim.x + threadIdx.x) >> 5;
    int lane = threadIdx.x & 31;
    if (warp >= n) return;
    const float* row = &g_xw[(size_t)warp * F];
    float ps[4], pd[4];
#pragma unroll
    for (int h = 0; h < 4; h++) {
        float v = row[h * 32 + lane];
        ps[h] = v * a_s[h * 32 + lane];
        pd[h] = v * a_d[h * 32 + lane];
    }
#pragma unroll
    for (int h = 0; h < 4; h++) {
#pragma unroll
        for (int o = 16; o > 0; o >>= 1) {
            ps[h] += __shfl_xor_sync(0xffffffff, ps[h], o);
            pd[h] += __shfl_xor_sync(0xffffffff, pd[h], o);
        }
    }
    if (lane == 0) {
        *(float4*)&g_ssrc[warp * 4] = make_float4(ps[0], ps[1], ps[2], ps[3]);
        *(float4*)&g_sdst[warp * 4] = make_float4(pd[0], pd[1], pd[2], pd[3]);
    }
}

// ---------------------------------------------------------------------------
// Edge pass A: segment max of leaky-relu scores (per dst, per head)
// ---------------------------------------------------------------------------
__global__ void edge_max_kernel(const int* __restrict__ ei, int E, int EP)
{
    int e = blockIdx.x * blockDim.x + threadIdx.x;
    if (e >= EP) return;
    int src, dst;
    if (e < E) { src = ei[e]; dst = ei[E + e]; } else { src = dst = e - E; }
    float4 ss = *(const float4*)&g_ssrc[src * 4];
    float4 sd = *(const float4*)&g_sdst[dst * 4];
    float* am = &g_amax[dst * 4];
    atomicMaxF(am + 0, lrelu(ss.x + sd.x));
    atomicMaxF(am + 1, lrelu(ss.y + sd.y));
    atomicMaxF(am + 2, lrelu(ss.z + sd.z));
    atomicMaxF(am + 3, lrelu(ss.w + sd.w));
}

// ---------------------------------------------------------------------------
// Edge pass B: softmax denominator (recompute score, exp, atomicAdd)
// ---------------------------------------------------------------------------
__global__ void edge_den_kernel(const int* __restrict__ ei, int E, int EP)
{
    int e = blockIdx.x * blockDim.x + threadIdx.x;
    if (e >= EP) return;
    int src, dst;
    if (e < E) { src = ei[e]; dst = ei[E + e]; } else { src = dst = e - E; }
    float4 ss = *(const float4*)&g_ssrc[src * 4];
    float4 sd = *(const float4*)&g_sdst[dst * 4];
    float4 am = *(const float4*)&g_amax[dst * 4];
    float* dn = &g_den[dst * 4];
    atomicAdd(dn + 0, expf(lrelu(ss.x + sd.x) - am.x));
    atomicAdd(dn + 1, expf(lrelu(ss.y + sd.y) - am.y));
    atomicAdd(dn + 2, expf(lrelu(ss.z + sd.z) - am.z));
    atomicAdd(dn + 3, expf(lrelu(ss.w + sd.w) - am.w));
}

// ---------------------------------------------------------------------------
// Edge pass C: weighted scatter-sum. One warp per edge; lane l owns the
// float4 at flat offset l*4 (head = l>>3). Coalesced 512B gather of xw[src],
// one float4 vector red per lane into acc[dst].
// ---------------------------------------------------------------------------
__global__ void edge_agg_kernel(const int* __restrict__ ei, int E, int EP)
{
    int gt = blockIdx.x * blockDim.x + threadIdx.x;
    int e = gt >> 5;
    if (e >= EP) return;
    int lane = gt & 31;
    int src, dst;
    if (e < E) { src = ei[e]; dst = ei[E + e]; } else { src = dst = e - E; }
    int h = lane >> 3;
    float ss = g_ssrc[src * 4 + h];
    float sd = g_sdst[dst * 4 + h];
    float am = g_amax[dst * 4 + h];
    float dn = g_den[dst * 4 + h];
    float attn = expf(lrelu(ss + sd) - am) / fmaxf(dn, 1e-16f);

    float4 v = *(const float4*)&g_xw[(size_t)src * F + lane * 4];
    v.x *= attn; v.y *= attn; v.z *= attn; v.w *= attn;
    atomicAdd((float4*)&g_acc[(size_t)dst * F + lane * 4], v);
}

// ---------------------------------------------------------------------------
// Epilogues
// ---------------------------------------------------------------------------
__global__ void fin_concat_kernel(const float* __restrict__ b)
{
    int idx = blockIdx.x * blockDim.x + threadIdx.x;
    if (idx >= NF) return;
    float v = g_acc[idx] + b[idx & 127];
    g_h[idx] = v > 0.f ? v : expm1f(v);   // ELU
}

__global__ void fin_mean_kernel(const float* __restrict__ b, float* __restrict__ outp)
{
    int idx = blockIdx.x * blockDim.x + threadIdx.x;
    if (idx >= NODES * 32) return;
    int c = idx & 31, row = idx >> 5;
    const float* a = &g_acc[(size_t)row * F];
    float s = a[c] + a[32 + c] + a[64 + c] + a[96 + c];
    outp[idx] = 0.25f * s + b[c];
}

// ---------------------------------------------------------------------------
// Host orchestration
// ---------------------------------------------------------------------------
static void run_layer(const float* in, int use_h, const float* W,
                      const float* a_s, const float* a_d, const float* b,
                      const int* ei, int E, int EP,
                      bool mean_out, float* outp)
{
    zero_kernel<<<(NF + 255) / 256, 256>>>();
    sgemm128<<<(NODES + 127) / 128, 256>>>(in, W, NODES, use_h);
    scores_kernel<<<(NODES + 3) / 4, 128>>>(a_s, a_d, NODES);
    edge_max_kernel<<<(EP + 255) / 256, 256>>>(ei, E, EP);
    edge_den_kernel<<<(EP + 255) / 256, 256>>>(ei, E, EP);
    {
        long long th = (long long)EP * 32;
        edge_agg_kernel<<<(unsigned)((th + 255) / 256), 256>>>(ei, E, EP);
    }
    if (mean_out)
        fin_mean_kernel<<<(NODES * 32 + 255) / 256, 256>>>(b, outp);
    else
        fin_concat_kernel<<<(NF + 255) / 256, 256>>>(b);
}

extern "C" void kernel_launch(void* const* d_in, const int* in_sizes, int n_in,
                              void* d_out, int out_size)
{
    const float* x   = (const float*)d_in[0];
    const int*   ei  = (const int*)d_in[1];
    const float* W1  = (const float*)d_in[2];
    const float* as1 = (const float*)d_in[3];
    const float* ad1 = (const float*)d_in[4];
    const float* b1  = (const float*)d_in[5];
    const float* W2  = (const float*)d_in[6];
    const float* as2 = (const float*)d_in[7];
    const float* ad2 = (const float*)d_in[8];
    const float* b2  = (const float*)d_in[9];
    const float* W3  = (const float*)d_in[10];
    const float* as3 = (const float*)d_in[11];
    const float* ad3 = (const float*)d_in[12];
    const float* b3  = (const float*)d_in[13];
    float* outp = (float*)d_out;

    int E  = in_sizes[1] / 2;
    int EP = E + NODES;

    run_layer(x,       0, W1, as1, ad1, b1, ei, E, EP, false, nullptr);
    run_layer(nullptr, 1, W2, as2, ad2, b2, ei, E, EP, false, nullptr);
    run_layer(nullptr, 1, W3, as3, ad3, b3, ei, E, EP, true,  outp);
}

// round 17
// speedup vs baseline: 1.4380x; 1.4380x over previous
#include <cuda_runtime.h>
#include <math.h>

// Problem constants (fixed by the reference)
#define NODES 100000
#define F 128          // feature width of every layer input/output (HEADS*HID)
#define NF (NODES * F)
#define N4 (NODES * 4)

// ---------------------------------------------------------------------------
// Scratch (device globals -- no allocation allowed)
// ---------------------------------------------------------------------------
__device__ float g_xw[NF];     // xw = input @ W for current layer  [N,4,32]
__device__ float g_acc[NF];    // per-dst weighted message accumulator
__device__ float g_h[NF];      // activations feeding the next layer
__device__ float g_ssrc[N4];   // per-node source attention logits  [N,4]
__device__ float g_sdst[N4];   // per-node dest   attention logits  [N,4]
__device__ float g_amax[N4];   // segment max per (dst, head)
__device__ float g_den[N4];    // segment softmax denominator

__device__ __forceinline__ float lrelu(float x) { return x > 0.f ? x : 0.2f * x; }

__device__ __forceinline__ void atomicMaxF(float* a, float v) {
    if (v >= 0.f) atomicMax((int*)a, __float_as_int(v));
    else          atomicMin((unsigned int*)a, __float_as_uint(v));
}

// ---------------------------------------------------------------------------
// init: acc = 0, amax = -inf, den = 0
// ---------------------------------------------------------------------------
__global__ void zero_kernel() {
    int idx = blockIdx.x * blockDim.x + threadIdx.x;
    if (idx < NF) g_acc[idx] = 0.f;
    if (idx < N4) {
        g_amax[idx] = __int_as_float(0xff800000);  // -inf
        g_den[idx]  = 0.f;
    }
}

// ---------------------------------------------------------------------------
// SGEMM: g_xw = A[M,128] @ W[128,128]    (BM=BN=128, BK=16, 8x8 per thread)
// use_h selects the g_h global as input (layers 2,3)
// ---------------------------------------------------------------------------
#define BK 16
#define ASTRIDE 132   // padded, keeps float4 alignment & spreads banks

__global__ __launch_bounds__(256) void sgemm128(const float* __restrict__ Ain,
                                                const float* __restrict__ B,
                                                int M, int use_h)
{
    const float* A = use_h ? g_h : Ain;
    __shared__ float As[BK * ASTRIDE];
    __shared__ float Bs[BK * 128];

    int tid  = threadIdx.x;
    int row0 = blockIdx.x * 128;
    int tx   = tid & 15;
    int ty   = tid >> 4;

    float acc[8][8];
#pragma unroll
    for (int r = 0; r < 8; r++)
#pragma unroll
        for (int c = 0; c < 8; c++) acc[r][c] = 0.f;

    for (int kt = 0; kt < F; kt += BK) {
        // A tile: 128 rows x 16 k, stored transposed As[k][row]
#pragma unroll
        for (int i = 0; i < 2; i++) {
            int f4  = tid * 2 + i;          // 0..511
            int row = f4 >> 2;
            int q4  = (f4 & 3) * 4;
            float4 v = make_float4(0.f, 0.f, 0.f, 0.f);
            int gr = row0 + row;
            if (gr < M) v = *(const float4*)&A[gr * F + kt + q4];
            As[(q4 + 0) * ASTRIDE + row] = v.x;
            As[(q4 + 1) * ASTRIDE + row] = v.y;
            As[(q4 + 2) * ASTRIDE + row] = v.z;
            As[(q4 + 3) * ASTRIDE + row] = v.w;
        }
        // B tile: 16 k x 128 cols
#pragma unroll
        for (int i = 0; i < 2; i++) {
            int f4 = tid * 2 + i;
            int k  = f4 >> 5;
            int j4 = (f4 & 31) * 4;
            *(float4*)&Bs[k * 128 + j4] = *(const float4*)&B[(kt + k) * F + j4];
        }
        __syncthreads();

#pragma unroll
        for (int kk = 0; kk < BK; kk++) {
            float4 a0 = *(const float4*)&As[kk * ASTRIDE + ty * 8];
            float4 a1 = *(const float4*)&As[kk * ASTRIDE + ty * 8 + 4];
            float4 b0 = *(const float4*)&Bs[kk * 128 + tx * 8];
            float4 b1 = *(const float4*)&Bs[kk * 128 + tx * 8 + 4];
            float av[8] = {a0.x, a0.y, a0.z, a0.w, a1.x, a1.y, a1.z, a1.w};
            float bv[8] = {b0.x, b0.y, b0.z, b0.w, b1.x, b1.y, b1.z, b1.w};
#pragma unroll
            for (int r = 0; r < 8; r++)
#pragma unroll
                for (int c = 0; c < 8; c++) acc[r][c] += av[r] * bv[c];
        }
        __syncthreads();
    }

#pragma unroll
    for (int r = 0; r < 8; r++) {
        int gr = row0 + ty * 8 + r;
        if (gr >= M) continue;
        float4 v0 = make_float4(acc[r][0], acc[r][1], acc[r][2], acc[r][3]);
        float4 v1 = make_float4(acc[r][4], acc[r][5], acc[r][6], acc[r][7]);
        *(float4*)&g_xw[gr * F + tx * 8]     = v0;
        *(float4*)&g_xw[gr * F + tx * 8 + 4] = v1;
    }
}

// ---------------------------------------------------------------------------
// Per-node attention logits: s_src[i,h] = sum_c xw[i,h,c]*a_src[h,c]  (warp/row)
// ---------------------------------------------------------------------------
__global__ void scores_kernel(const float* __restrict__ a_s,
                              const float* __restrict__ a_d, int n)
{
    int warp = (blockIdx.x * blockDim.x + threadIdx.x) >> 5;
    int lane = threadIdx.x & 31;
    if (warp >= n) return;
    const float* row = &g_xw[(size_t)warp * F];
    float ps[4], pd[4];
#pragma unroll
    for (int h = 0; h < 4; h++) {
        float v = row[h * 32 + lane];
        ps[h] = v * a_s[h * 32 + lane];
        pd[h] = v * a_d[h * 32 + lane];
    }
#pragma unroll
    for (int h = 0; h < 4; h++) {
#pragma unroll
        for (int o = 16; o > 0; o >>= 1) {
            ps[h] += __shfl_xor_sync(0xffffffff, ps[h], o);
            pd[h] += __shfl_xor_sync(0xffffffff, pd[h], o);
        }
    }
    if (lane == 0) {
        *(float4*)&g_ssrc[warp * 4] = make_float4(ps[0], ps[1], ps[2], ps[3]);
        *(float4*)&g_sdst[warp * 4] = make_float4(pd[0], pd[1], pd[2], pd[3]);
    }
}

// ---------------------------------------------------------------------------
// Edge pass A: segment max of leaky-relu scores (per dst, per head)
// ---------------------------------------------------------------------------
__global__ void edge_max_kernel(const int* __restrict__ ei, int E, int EP)
{
    int e = blockIdx.x * blockDim.x + threadIdx.x;
    if (e >= EP) return;
    int src, dst;
    if (e < E) { src = ei[e]; dst = ei[E + e]; } else { src = dst = e - E; }
    float4 ss = *(const float4*)&g_ssrc[src * 4];
    float4 sd = *(const float4*)&g_sdst[dst * 4];
    float* am = &g_amax[dst * 4];
    atomicMaxF(am + 0, lrelu(ss.x + sd.x));
    atomicMaxF(am + 1, lrelu(ss.y + sd.y));
    atomicMaxF(am + 2, lrelu(ss.z + sd.z));
    atomicMaxF(am + 3, lrelu(ss.w + sd.w));
}

// ---------------------------------------------------------------------------
// Edge pass B: softmax denominator (recompute score, exp, atomicAdd)
// ---------------------------------------------------------------------------
__global__ void edge_den_kernel(const int* __restrict__ ei, int E, int EP)
{
    int e = blockIdx.x * blockDim.x + threadIdx.x;
    if (e >= EP) return;
    int src, dst;
    if (e < E) { src = ei[e]; dst = ei[E + e]; } else { src = dst = e - E; }
    float4 ss = *(const float4*)&g_ssrc[src * 4];
    float4 sd = *(const float4*)&g_sdst[dst * 4];
    float4 am = *(const float4*)&g_amax[dst * 4];
    float* dn = &g_den[dst * 4];
    atomicAdd(dn + 0, expf(lrelu(ss.x + sd.x) - am.x));
    atomicAdd(dn + 1, expf(lrelu(ss.y + sd.y) - am.y));
    atomicAdd(dn + 2, expf(lrelu(ss.z + sd.z) - am.z));
    atomicAdd(dn + 3, expf(lrelu(ss.w + sd.w) - am.w));
}

// ---------------------------------------------------------------------------
// Edge pass C: weighted scatter-sum. One warp per edge; lane l owns the
// float4 at flat offset l*4 (head = l>>3). Coalesced 512B gather of xw[src],
// one float4 vector red per lane into acc[dst].
// ---------------------------------------------------------------------------
__global__ void edge_agg_kernel(const int* __restrict__ ei, int E, int EP)
{
    int gt = blockIdx.x * blockDim.x + threadIdx.x;
    int e = gt >> 5;
    if (e >= EP) return;
    int lane = gt & 31;
    int src, dst;
    if (e < E) { src = ei[e]; dst = ei[E + e]; } else { src = dst = e - E; }
    int h = lane >> 3;
    float ss = g_ssrc[src * 4 + h];
    float sd = g_sdst[dst * 4 + h];
    float am = g_amax[dst * 4 + h];
    float dn = g_den[dst * 4 + h];
    float attn = expf(lrelu(ss + sd) - am) / fmaxf(dn, 1e-16f);

    float4 v = *(const float4*)&g_xw[(size_t)src * F + lane * 4];
    v.x *= attn; v.y *= attn; v.z *= attn; v.w *= attn;
    atomicAdd((float4*)&g_acc[(size_t)dst * F + lane * 4], v);
}

// ---------------------------------------------------------------------------
// Epilogues
// ---------------------------------------------------------------------------
__global__ void fin_concat_kernel(const float* __restrict__ b)
{
    int idx = blockIdx.x * blockDim.x + threadIdx.x;
    if (idx >= NF) return;
    float v = g_acc[idx] + b[idx & 127];
    g_h[idx] = v > 0.f ? v : expm1f(v);   // ELU
}

__global__ void fin_mean_kernel(const float* __restrict__ b, float* __restrict__ outp)
{
    int idx = blockIdx.x * blockDim.x + threadIdx.x;
    if (idx >= NODES * 32) return;
    int c = idx & 31, row = idx >> 5;
    const float* a = &g_acc[(size_t)row * F];
    float s = a[c] + a[32 + c] + a[64 + c] + a[96 + c];
    outp[idx] = 0.25f * s + b[c];
}

// ---------------------------------------------------------------------------
// Host orchestration
// ---------------------------------------------------------------------------
static void run_layer(const float* in, int use_h, const float* W,
                      const float* a_s, const float* a_d, const float* b,
                      const int* ei, int E, int EP,
                      bool mean_out, float* outp)
{
    zero_kernel<<<(NF + 255) / 256, 256>>>();
    sgemm128<<<(NODES + 127) / 128, 256>>>(in, W, NODES, use_h);
    scores_kernel<<<(NODES + 3) / 4, 128>>>(a_s, a_d, NODES);
    edge_max_kernel<<<(EP + 255) / 256, 256>>>(ei, E, EP);
    edge_den_kernel<<<(EP + 255) / 256, 256>>>(ei, E, EP);
    {
        long long th = (long long)EP * 32;
        edge_agg_kernel<<<(unsigned)((th + 255) / 256), 256>>>(ei, E, EP);
    }
    if (mean_out)
        fin_mean_kernel<<<(NODES * 32 + 255) / 256, 256>>>(b, outp);
    else
        fin_concat_kernel<<<(NF + 255) / 256, 256>>>(b);
}

extern "C" void kernel_launch(void* const* d_in, const int* in_sizes, int n_in,
                              void* d_out, int out_size)
{
    const float* x   = (const float*)d_in[0];
    const int*   ei  = (const int*)d_in[1];
    const float* W1  = (const float*)d_in[2];
    const float* as1 = (const float*)d_in[3];
    const float* ad1 = (const float*)d_in[4];
    const float* b1  = (const float*)d_in[5];
    const float* W2  = (const float*)d_in[6];
    const float* as2 = (const float*)d_in[7];
    const float* ad2 = (const float*)d_in[8];
    const float* b2  = (const float*)d_in[9];
    const float* W3  = (const float*)d_in[10];
    const float* as3 = (const float*)d_in[11];
    const float* ad3 = (const float*)d_in[12];
    const float* b3  = (const float*)d_in[13];
    float* outp = (float*)d_out;

    int E  = in_sizes[1] / 2;
    int EP = E + NODES;

    run_layer(x,       0, W1, as1, ad1, b1, ei, E, EP, false, nullptr);
    run_layer(nullptr, 1, W2, as2, ad2, b2, ei, E, EP, false, nullptr);
    run_layer(nullptr, 1, W3, as3, ad3, b3, ei, E, EP, true,  outp);
}